// round 10
// baseline (speedup 1.0000x reference)
#include <cuda_runtime.h>
#include <math_constants.h>
#include <cstdint>

// FLoss: weighted BCE, weights = W / (dist_to_argmax_centroid + 1)
// input  d_in[0]: [B,1,T,W,W] f32  (same linear layout as [B,T,W,W])
// target d_in[1]: [B,T,W,W]   f32
// out: scalar f32 = -mean(w * (t*clip(log p,-100) + (1-t)*clip(log1p(-p),-100)))
//
// Fused TWO-phase kernel, one 1024-thread CTA per frame, 2 CTAs/SM:
//   phase 1: max + centroid in ONE scan (branchless running chains — proven
//            to run at DRAM roofline in the split version)
//   phase 2: weighted BCE; target re-read hits L2 (67MB < 126MB L2),
//            input streamed with .cs. MUFU-bound, memory hidden under it.

#define FRAME_ELEMS4 16384                 // 65536 elems / 4

__device__ double   g_acc;                 // zero-init; last CTA resets each replay
__device__ unsigned g_done;

#define LOG2_CLAMP (-144.26950408889634f)  // -100 / ln(2)
#define LN2F        (0.6931471805599453f)

__global__ __launch_bounds__(1024, 2) void floss_fused_kernel(const float* __restrict__ inp,
                                                              const float* __restrict__ tgt,
                                                              float* __restrict__ out,
                                                              double inv_n)
{
    const int f   = blockIdx.x;
    const int tid = threadIdx.x;
    const float4* T = reinterpret_cast<const float4*>(tgt) + (size_t)f * FRAME_ELEMS4;
    const float4* P = reinterpret_cast<const float4*>(inp) + (size_t)f * FRAME_ELEMS4;

    __shared__ float s_wmax[32];
    __shared__ float s_gmax, s_sx, s_sy, s_cnt, s_cx, s_cy;

    // ---- phase 1: max + centroid of maximal pixels, single scan -----------
    // 4 independent branchless running chains; exact target==max semantics.
    {
        float lm[4], cn[4], sx[4], sy[4];
        #pragma unroll
        for (int c = 0; c < 4; c++) { lm[c] = -CUDART_INF_F; cn[c] = 0.f; sx[c] = 0.f; sy[c] = 0.f; }

        #pragma unroll 4
        for (int k = 0; k < 16; k++) {
            const int e4 = tid + k * 1024;
            const float4 v = __ldg(T + e4);
            const int e = e4 * 4;
            const float row  = (float)(e >> 8);
            const float col0 = (float)(e & 255);
            const float vals[4] = {v.x, v.y, v.z, v.w};
            #pragma unroll
            for (int c = 0; c < 4; c++) {
                const float val = vals[c];
                const float col = col0 + (float)c;
                const bool gt = (val >  lm[c]);
                const bool eq = (val == lm[c]);
                cn[c] = gt ? 1.f : (cn[c] + (eq ? 1.f : 0.f));
                sx[c] = gt ? row : (sx[c] + (eq ? row : 0.f));
                sy[c] = gt ? col : (sy[c] + (eq ? col : 0.f));
                lm[c] = fmaxf(lm[c], val);
            }
        }

        // merge 4 chains
        float lmax = lm[0], cnt = cn[0], tsx = sx[0], tsy = sy[0];
        #pragma unroll
        for (int c = 1; c < 4; c++) {
            if (lm[c] > lmax)       { lmax = lm[c]; cnt = cn[c]; tsx = sx[c]; tsy = sy[c]; }
            else if (lm[c] == lmax) { cnt += cn[c]; tsx += sx[c]; tsy += sy[c]; }
        }

        // block max reduction
        float wm = lmax;
        #pragma unroll
        for (int o = 16; o; o >>= 1) wm = fmaxf(wm, __shfl_xor_sync(0xffffffffu, wm, o));
        if ((tid & 31) == 0) s_wmax[tid >> 5] = wm;
        if (tid == 0) { s_sx = 0.f; s_sy = 0.f; s_cnt = 0.f; }
        __syncthreads();
        if (tid < 32) {
            float m = s_wmax[tid];
            #pragma unroll
            for (int o = 16; o; o >>= 1) m = fmaxf(m, __shfl_xor_sync(0xffffffffu, m, o));
            if (tid == 0) s_gmax = m;
        }
        __syncthreads();

        if (lmax == s_gmax) {            // rare: only threads holding the frame max
            atomicAdd(&s_cnt, cnt);
            atomicAdd(&s_sx,  tsx);
            atomicAdd(&s_sy,  tsy);
        }
        __syncthreads();
        if (tid == 0) { s_cx = s_sx / s_cnt; s_cy = s_sy / s_cnt; }
        __syncthreads();
    }
    const float cx = s_cx;
    const float cy = s_cy;

    // ---- phase 2: weighted BCE (forward; target from L2, input streamed) --
    // 1024 threads = 16 rows x 64 float4-cols per step; row advances by 16.
    const float col0 = (float)((tid & 63) * 4) - cy;   // dj for lane c: col0 + c
    float di = (float)(tid >> 6) - cx;

    float lsum = 0.f;
    #pragma unroll 2
    for (int k = 0; k < 16; k++) {
        const int e4 = tid + k * 1024;
        const float4 t4 = __ldg (T + e4);       // L2 hit (target resident)
        const float4 p4 = __ldcs(P + e4);       // DRAM stream, evict-first

        const float di2 = di * di;
        di += 16.0f;

        #pragma unroll
        for (int c = 0; c < 4; c++) {
            const float p = (c == 0) ? p4.x : (c == 1) ? p4.y : (c == 2) ? p4.z : p4.w;
            const float t = (c == 0) ? t4.x : (c == 1) ? t4.y : (c == 2) ? t4.z : t4.w;

            const float dj = col0 + (float)c;
            const float s  = fmaf(dj, dj, di2);
            float dist, wrcp;
            asm("sqrt.approx.f32 %0, %1;" : "=f"(dist) : "f"(s));   // sqrt.approx(0)=0
            asm("rcp.approx.f32 %0, %1;"  : "=f"(wrcp) : "f"(dist + 1.0f));

            float lp2, lq2;
            asm("lg2.approx.f32 %0, %1;" : "=f"(lp2) : "f"(p));
            asm("lg2.approx.f32 %0, %1;" : "=f"(lq2) : "f"(1.0f - p));
            lp2 = fmaxf(lp2, LOG2_CLAMP);
            lq2 = fmaxf(lq2, LOG2_CLAMP);
            const float term = fmaf(t, lp2 - lq2, lq2);     // log2 domain
            lsum = fmaf(256.0f * wrcp, term, lsum);
        }
    }
    lsum *= LN2F;

    // ---- reduce + last-CTA finalize ----------------------------------------
    __shared__ double s_acc;
    if (tid == 0) s_acc = 0.0;
    __syncthreads();

    #pragma unroll
    for (int o = 16; o; o >>= 1) lsum += __shfl_xor_sync(0xffffffffu, lsum, o);
    if ((tid & 31) == 0) atomicAdd(&s_acc, (double)lsum);
    __syncthreads();

    if (tid == 0) {
        atomicAdd(&g_acc, s_acc);
        __threadfence();
        const unsigned tk = atomicAdd(&g_done, 1u);
        if (tk == gridDim.x - 1) {                // last CTA of this replay
            const double total = atomicAdd(&g_acc, 0.0);
            out[0] = (float)(-total * inv_n);
            g_acc = 0.0;                          // reset for next graph replay
            __threadfence();
            atomicExch(&g_done, 0u);
        }
    }
}

extern "C" void kernel_launch(void* const* d_in, const int* in_sizes, int n_in,
                              void* d_out, int out_size)
{
    const float* inp = (const float*)d_in[0];
    const float* tgt = (const float*)d_in[1];
    float* out = (float*)d_out;

    const int n       = in_sizes[1];       // B*T*W*W
    const int nframes = n >> 16;           // 65536 elems per frame

    floss_fused_kernel<<<nframes, 1024>>>(inp, tgt, out, 1.0 / (double)n);
}

// round 11
// speedup vs baseline: 1.1474x; 1.1474x over previous
#include <cuda_runtime.h>
#include <math_constants.h>
#include <cstdint>

// FLoss: weighted BCE, weights = W / (dist_to_argmax_centroid + 1)
// input  d_in[0]: [B,1,T,W,W] f32  (same linear layout as [B,T,W,W])
// target d_in[1]: [B,T,W,W]   f32
// out: scalar f32 = -mean(w * (t*clip(log p,-100) + (1-t)*clip(log1p(-p),-100)))

#define FRAME_ELEMS4 16384                 // 65536 elems / 4
#define MAX_FRAMES 4096

__device__ float2   g_c[MAX_FRAMES];       // per-frame centroid (cx, cy)
__device__ double   g_acc;
__device__ unsigned g_done;

#define LOG2_CLAMP (-144.26950408889634f)  // -100 / ln(2)
#define LN2F        (0.6931471805599453f)

// Loss grid: stride = LOSS_GRID*256 must be a multiple of 16384 (frame size in
// float4) so that per-thread row/col are loop-invariant and the frame index
// advances by a constant. 2368*256 = 37*16384.
#define LOSS_GRID   2368
#define FRAME_STEP  37                     // (LOSS_GRID*256)/16384

// ---------------------------------------------------------------------------
// Kernel 1: per-frame max + centroid, single pass, branchless 4-chain.
// One CTA (1024 threads) per frame. Measured ~8.8us (~7.6 TB/s, at roofline).
// Exact tie semantics (target == max), identical to reference.
// ---------------------------------------------------------------------------
__global__ __launch_bounds__(1024) void frame_stats_kernel(const float* __restrict__ tgt)
{
    const int f   = blockIdx.x;
    const int tid = threadIdx.x;
    const float4* base = reinterpret_cast<const float4*>(tgt) + (size_t)f * FRAME_ELEMS4;

    float lm[4], cn[4], sx[4], sy[4];
    #pragma unroll
    for (int c = 0; c < 4; c++) { lm[c] = -CUDART_INF_F; cn[c] = 0.f; sx[c] = 0.f; sy[c] = 0.f; }

    #pragma unroll
    for (int k = 0; k < 16; k++) {
        const int e4 = tid + k * 1024;
        const float4 v = __ldg(base + e4);
        const int e = e4 * 4;
        const float row  = (float)(e >> 8);
        const float col0 = (float)(e & 255);
        const float vals[4] = {v.x, v.y, v.z, v.w};
        #pragma unroll
        for (int c = 0; c < 4; c++) {
            const float val = vals[c];
            const float col = col0 + (float)c;
            const bool gt = (val >  lm[c]);
            const bool eq = (val == lm[c]);
            cn[c] = gt ? 1.f : (cn[c] + (eq ? 1.f : 0.f));
            sx[c] = gt ? row : (sx[c] + (eq ? row : 0.f));
            sy[c] = gt ? col : (sy[c] + (eq ? col : 0.f));
            lm[c] = fmaxf(lm[c], val);
        }
    }

    float lmax = lm[0], cnt = cn[0], tsx = sx[0], tsy = sy[0];
    #pragma unroll
    for (int c = 1; c < 4; c++) {
        if (lm[c] > lmax)       { lmax = lm[c]; cnt = cn[c]; tsx = sx[c]; tsy = sy[c]; }
        else if (lm[c] == lmax) { cnt += cn[c]; tsx += sx[c]; tsy += sy[c]; }
    }

    __shared__ float s_wmax[32];
    __shared__ float s_gmax, s_sx, s_sy, s_cnt;

    float wm = lmax;
    #pragma unroll
    for (int o = 16; o; o >>= 1) wm = fmaxf(wm, __shfl_xor_sync(0xffffffffu, wm, o));
    if ((tid & 31) == 0) s_wmax[tid >> 5] = wm;
    if (tid == 0) { s_sx = 0.f; s_sy = 0.f; s_cnt = 0.f; }
    __syncthreads();
    if (tid < 32) {
        float m = s_wmax[tid];
        #pragma unroll
        for (int o = 16; o; o >>= 1) m = fmaxf(m, __shfl_xor_sync(0xffffffffu, m, o));
        if (tid == 0) s_gmax = m;
    }
    __syncthreads();

    if (lmax == s_gmax) {
        atomicAdd(&s_cnt, cnt);
        atomicAdd(&s_sx,  tsx);
        atomicAdd(&s_sy,  tsy);
    }
    __syncthreads();

    if (tid == 0) {
        g_c[f] = make_float2(s_sx / s_cnt, s_sy / s_cnt);
        if (f == 0) { g_acc = 0.0; g_done = 0u; }   // per-replay reset (before loss)
    }
}

// ---------------------------------------------------------------------------
// Kernel 2: weighted BCE. Grid-stride with frame-aligned stride: per-thread
// row/col are LOOP-INVARIANT (no index ALU / I2F in the loop); frame index
// advances by +37. Plain __ldg on both streams. Last CTA finalizes.
// ---------------------------------------------------------------------------
__global__ __launch_bounds__(256) void loss_kernel(const float* __restrict__ inp,
                                                   const float* __restrict__ tgt,
                                                   int total4,
                                                   float* __restrict__ out,
                                                   double inv_n)
{
    __shared__ double s_acc;
    if (threadIdx.x == 0) s_acc = 0.0;
    __syncthreads();

    const float4* P = reinterpret_cast<const float4*>(inp);
    const float4* T = reinterpret_cast<const float4*>(tgt);

    const int i0 = blockIdx.x * blockDim.x + threadIdx.x;

    // loop-invariant geometry (stride is a multiple of 16384 float4)
    const float rowf = (float)((i0 >> 6) & 255);
    const float j0   = (float)((i0 & 63) * 4);
    int f = i0 >> 14;

    const int stride = LOSS_GRID * 256;

    float lsum = 0.f;
    for (int i = i0; i < total4; i += stride, f += FRAME_STEP) {
        const float2 cc = __ldg(&g_c[f]);          // 2KB table, L1-resident

        const float4 p4 = __ldg(P + i);
        const float4 t4 = __ldg(T + i);

        const float di  = rowf - cc.x;
        const float di2 = di * di;
        const float jb  = j0 - cc.y;               // dj for lane c = jb + c

        #pragma unroll
        for (int c = 0; c < 4; c++) {
            const float p = (c == 0) ? p4.x : (c == 1) ? p4.y : (c == 2) ? p4.z : p4.w;
            const float t = (c == 0) ? t4.x : (c == 1) ? t4.y : (c == 2) ? t4.z : t4.w;

            const float dj = jb + (float)c;
            const float s  = fmaf(dj, dj, di2);
            float dist, wrcp;
            asm("sqrt.approx.f32 %0, %1;" : "=f"(dist) : "f"(s));    // sqrt.approx(0)=0
            asm("rcp.approx.f32 %0, %1;"  : "=f"(wrcp) : "f"(dist + 1.0f));

            float lp2, lq2;
            asm("lg2.approx.f32 %0, %1;" : "=f"(lp2) : "f"(p));
            asm("lg2.approx.f32 %0, %1;" : "=f"(lq2) : "f"(1.0f - p));
            lp2 = fmaxf(lp2, LOG2_CLAMP);
            lq2 = fmaxf(lq2, LOG2_CLAMP);
            const float term = fmaf(t, lp2 - lq2, lq2);   // log2 domain
            lsum = fmaf(256.0f * wrcp, term, lsum);
        }
    }
    lsum *= LN2F;

    #pragma unroll
    for (int o = 16; o; o >>= 1) lsum += __shfl_xor_sync(0xffffffffu, lsum, o);
    if ((threadIdx.x & 31) == 0) atomicAdd(&s_acc, (double)lsum);
    __syncthreads();

    if (threadIdx.x == 0) {
        atomicAdd(&g_acc, s_acc);
        __threadfence();
        const unsigned t = atomicAdd(&g_done, 1u);
        if (t == gridDim.x - 1) {
            const double total = atomicAdd(&g_acc, 0.0);
            out[0] = (float)(-total * inv_n);
        }
    }
}

extern "C" void kernel_launch(void* const* d_in, const int* in_sizes, int n_in,
                              void* d_out, int out_size)
{
    const float* inp = (const float*)d_in[0];
    const float* tgt = (const float*)d_in[1];
    float* out = (float*)d_out;

    const int n       = in_sizes[1];       // B*T*W*W
    const int nframes = n >> 16;
    const int total4  = n >> 2;

    frame_stats_kernel<<<nframes, 1024>>>(tgt);
    loss_kernel<<<LOSS_GRID, 256>>>(inp, tgt, total4, out, 1.0 / (double)n);
}

// round 13
// speedup vs baseline: 1.1535x; 1.0054x over previous
#include <cuda_runtime.h>
#include <math_constants.h>
#include <cstdint>

// FLoss: weighted BCE, weights = W / (dist_to_argmax_centroid + 1)
// input  d_in[0]: [B,1,T,W,W] f32  (same linear layout as [B,T,W,W])
// target d_in[1]: [B,T,W,W]   f32
// out: scalar f32 = -mean(w * (t*clip(log p,-100) + (1-t)*clip(log1p(-p),-100)))
//
// L2-residency play (fixed encoding): createpolicy + ld.L2::cache_hint.
// Stats reads target with evict_last policy (67MB pinned in 126MB L2);
// loss re-reads target as L2 hits and streams input with evict_first.

#define FRAME_ELEMS4 16384                 // 65536 elems / 4
#define MAX_FRAMES 4096

__device__ float2   g_c[MAX_FRAMES];       // per-frame centroid (cx, cy)
__device__ double   g_acc;
__device__ unsigned g_done;

#define LOG2_CLAMP (-144.26950408889634f)  // -100 / ln(2)
#define LN2F        (0.6931471805599453f)

#define LOSS_GRID   2368                   // stride 2368*256 = 37*16384
#define FRAME_STEP  37

__device__ __forceinline__ unsigned long long mk_policy_evict_last() {
    unsigned long long pol;
    asm("createpolicy.fractional.L2::evict_last.b64 %0, 1.0;" : "=l"(pol));
    return pol;
}
__device__ __forceinline__ unsigned long long mk_policy_evict_first() {
    unsigned long long pol;
    asm("createpolicy.fractional.L2::evict_first.b64 %0, 1.0;" : "=l"(pol));
    return pol;
}
__device__ __forceinline__ float4 ldg_hint(const float4* p, unsigned long long pol) {
    float4 v;
    asm volatile("ld.global.nc.L2::cache_hint.v4.f32 {%0,%1,%2,%3}, [%4], %5;"
                 : "=f"(v.x), "=f"(v.y), "=f"(v.z), "=f"(v.w) : "l"(p), "l"(pol));
    return v;
}

// ---------------------------------------------------------------------------
// Kernel 1: per-frame max + centroid, single pass, branchless 4-chain.
// One CTA (1024 threads) per frame; target tagged evict_last in L2.
// Exact tie semantics (target == max), identical to reference.
// ---------------------------------------------------------------------------
__global__ __launch_bounds__(1024) void frame_stats_kernel(const float* __restrict__ tgt)
{
    const int f   = blockIdx.x;
    const int tid = threadIdx.x;
    const float4* base = reinterpret_cast<const float4*>(tgt) + (size_t)f * FRAME_ELEMS4;
    const unsigned long long pol = mk_policy_evict_last();

    float lm[4], cn[4], sx[4], sy[4];
    #pragma unroll
    for (int c = 0; c < 4; c++) { lm[c] = -CUDART_INF_F; cn[c] = 0.f; sx[c] = 0.f; sy[c] = 0.f; }

    #pragma unroll
    for (int k = 0; k < 16; k++) {
        const int e4 = tid + k * 1024;
        const float4 v = ldg_hint(base + e4, pol);
        const int e = e4 * 4;
        const float row  = (float)(e >> 8);
        const float col0 = (float)(e & 255);
        const float vals[4] = {v.x, v.y, v.z, v.w};
        #pragma unroll
        for (int c = 0; c < 4; c++) {
            const float val = vals[c];
            const float col = col0 + (float)c;
            const bool gt = (val >  lm[c]);
            const bool eq = (val == lm[c]);
            cn[c] = gt ? 1.f : (cn[c] + (eq ? 1.f : 0.f));
            sx[c] = gt ? row : (sx[c] + (eq ? row : 0.f));
            sy[c] = gt ? col : (sy[c] + (eq ? col : 0.f));
            lm[c] = fmaxf(lm[c], val);
        }
    }

    float lmax = lm[0], cnt = cn[0], tsx = sx[0], tsy = sy[0];
    #pragma unroll
    for (int c = 1; c < 4; c++) {
        if (lm[c] > lmax)       { lmax = lm[c]; cnt = cn[c]; tsx = sx[c]; tsy = sy[c]; }
        else if (lm[c] == lmax) { cnt += cn[c]; tsx += sx[c]; tsy += sy[c]; }
    }

    __shared__ float s_wmax[32];
    __shared__ float s_gmax, s_sx, s_sy, s_cnt;

    float wm = lmax;
    #pragma unroll
    for (int o = 16; o; o >>= 1) wm = fmaxf(wm, __shfl_xor_sync(0xffffffffu, wm, o));
    if ((tid & 31) == 0) s_wmax[tid >> 5] = wm;
    if (tid == 0) { s_sx = 0.f; s_sy = 0.f; s_cnt = 0.f; }
    __syncthreads();
    if (tid < 32) {
        float m = s_wmax[tid];
        #pragma unroll
        for (int o = 16; o; o >>= 1) m = fmaxf(m, __shfl_xor_sync(0xffffffffu, m, o));
        if (tid == 0) s_gmax = m;
    }
    __syncthreads();

    if (lmax == s_gmax) {
        atomicAdd(&s_cnt, cnt);
        atomicAdd(&s_sx,  tsx);
        atomicAdd(&s_sy,  tsy);
    }
    __syncthreads();

    if (tid == 0) {
        g_c[f] = make_float2(s_sx / s_cnt, s_sy / s_cnt);
        if (f == 0) { g_acc = 0.0; g_done = 0u; }   // per-replay reset (before loss)
    }
}

// ---------------------------------------------------------------------------
// Kernel 2: weighted BCE. Frame-aligned grid-stride (loop-invariant row/col),
// target via evict_last policy (L2 hits), input via evict_first (stream).
// Two accumulators break the serial FMA chain. Last CTA finalizes.
// ---------------------------------------------------------------------------
__global__ __launch_bounds__(256) void loss_kernel(const float* __restrict__ inp,
                                                   const float* __restrict__ tgt,
                                                   int total4,
                                                   float* __restrict__ out,
                                                   double inv_n)
{
    __shared__ double s_acc;
    if (threadIdx.x == 0) s_acc = 0.0;
    __syncthreads();

    const float4* P = reinterpret_cast<const float4*>(inp);
    const float4* T = reinterpret_cast<const float4*>(tgt);
    const unsigned long long pol_first = mk_policy_evict_first();
    const unsigned long long pol_last  = mk_policy_evict_last();

    const int i0 = blockIdx.x * blockDim.x + threadIdx.x;

    // loop-invariant geometry (stride is a multiple of 16384 float4)
    const float rowf = (float)((i0 >> 6) & 255);
    const float j0   = (float)((i0 & 63) * 4);
    int f = i0 >> 14;

    const int stride = LOSS_GRID * 256;

    float lsum0 = 0.f, lsum1 = 0.f;
    for (int i = i0; i < total4; i += stride, f += FRAME_STEP) {
        const float2 cc = __ldg(&g_c[f]);              // 2KB table, L1-resident

        const float4 p4 = ldg_hint(P + i, pol_first);  // DRAM stream
        const float4 t4 = ldg_hint(T + i, pol_last);   // L2 hit (pinned by stats)

        const float di  = rowf - cc.x;
        const float di2 = di * di;
        const float jb  = j0 - cc.y;                   // dj for lane c = jb + c

        #pragma unroll
        for (int c = 0; c < 4; c++) {
            const float p = (c == 0) ? p4.x : (c == 1) ? p4.y : (c == 2) ? p4.z : p4.w;
            const float t = (c == 0) ? t4.x : (c == 1) ? t4.y : (c == 2) ? t4.z : t4.w;

            const float dj = jb + (float)c;
            const float s  = fmaf(dj, dj, di2);
            float dist, wrcp;
            asm("sqrt.approx.f32 %0, %1;" : "=f"(dist) : "f"(s));    // sqrt.approx(0)=0
            asm("rcp.approx.f32 %0, %1;"  : "=f"(wrcp) : "f"(dist + 1.0f));

            float lp2, lq2;
            asm("lg2.approx.f32 %0, %1;" : "=f"(lp2) : "f"(p));
            asm("lg2.approx.f32 %0, %1;" : "=f"(lq2) : "f"(1.0f - p));
            lp2 = fmaxf(lp2, LOG2_CLAMP);
            lq2 = fmaxf(lq2, LOG2_CLAMP);
            const float term = fmaf(t, lp2 - lq2, lq2);   // log2 domain
            if (c & 1) lsum1 = fmaf(256.0f * wrcp, term, lsum1);
            else       lsum0 = fmaf(256.0f * wrcp, term, lsum0);
        }
    }
    float lsum = (lsum0 + lsum1) * LN2F;

    #pragma unroll
    for (int o = 16; o; o >>= 1) lsum += __shfl_xor_sync(0xffffffffu, lsum, o);
    if ((threadIdx.x & 31) == 0) atomicAdd(&s_acc, (double)lsum);
    __syncthreads();

    if (threadIdx.x == 0) {
        atomicAdd(&g_acc, s_acc);
        __threadfence();
        const unsigned t = atomicAdd(&g_done, 1u);
        if (t == gridDim.x - 1) {
            const double total = atomicAdd(&g_acc, 0.0);
            out[0] = (float)(-total * inv_n);
        }
    }
}

extern "C" void kernel_launch(void* const* d_in, const int* in_sizes, int n_in,
                              void* d_out, int out_size)
{
    const float* inp = (const float*)d_in[0];
    const float* tgt = (const float*)d_in[1];
    float* out = (float*)d_out;

    const int n       = in_sizes[1];       // B*T*W*W
    const int nframes = n >> 16;
    const int total4  = n >> 2;

    frame_stats_kernel<<<nframes, 1024>>>(tgt);
    loss_kernel<<<LOSS_GRID, 256>>>(inp, tgt, total4, out, 1.0 / (double)n);
}